// round 16
// baseline (speedup 1.0000x reference)
#include <cuda_runtime.h>
#include <math.h>
#include <stdint.h>

// Problem constants (fixed by setup_inputs)
#define N_NODES 32768
#define NB      64
#define LSEQ    512
#define DIM     256
#define HID     512
#define GI3     1536   // 3*HID
#define EDGES   524288

// ---------------- f32x2 packed math (sm_103a) ----------------
#define FMA2(d, a, b, c) \
    asm("fma.rn.f32x2 %0, %1, %2, %3;" : "=l"(d) : "l"(a), "l"(b), "l"(c))
#define SPLAT2(d, s) \
    asm("mov.b64 %0, {%1, %2};" : "=l"(d) : "f"(s), "f"(s))

__device__ __forceinline__ int ld_acquire_gpu(const int* p) {
    int v;
    asm volatile("ld.global.acquire.gpu.b32 %0, [%1];" : "=r"(v) : "l"(p) : "memory");
    return v;
}
__device__ __forceinline__ void red_release_gpu(int* p, int v) {
    asm volatile("red.global.add.release.gpu.s32 [%0], %1;" :: "l"(p), "r"(v) : "memory");
}
__device__ __forceinline__ void st_release_gpu(int* p, int v) {
    asm volatile("st.global.release.gpu.b32 [%0], %1;" :: "l"(p), "r"(v) : "memory");
}

// ---------------- scratch (static device globals; no allocation) ----------------
__device__ float g_t  [(size_t)N_NODES * HID];
__device__ float g_h1 [(size_t)N_NODES * HID];
__device__ float g_h2 [(size_t)N_NODES * HID];
__device__ float g_gi [(size_t)N_NODES * GI3];
__device__ int   g_deg [N_NODES];
__device__ float g_dinv[N_NODES];
__device__ int   g_off [N_NODES + 1];
__device__ int   g_cursor[N_NODES];
__device__ int   g_csrc[EDGES];
__device__ float g_ccoef[EDGES];
__device__ float g_hbuf[2][NB * HID];
__device__ float g_hsum[NB * HID];
__device__ int   g_bar[8 * 32];   // one counter per graph-group, separate 128B lines
__device__ int   g_giprog[3 * 32]; // chunk-ready flags (one per 128B line)

// ---------------- degree / CSR build ----------------
__global__ void k_count(const int* __restrict__ dst, int* __restrict__ deg, int E) {
    int i = blockIdx.x * 256 + threadIdx.x;
    if (i < E) atomicAdd(&deg[dst[i]], 1);
}

__global__ void k_dinv(const int* __restrict__ deg, float* __restrict__ dinv) {
    int i = blockIdx.x * 256 + threadIdx.x;
    if (i < N_NODES) dinv[i] = rsqrtf((float)(deg[i] + 1));  // +1 self loop
}

__global__ void __launch_bounds__(1024) k_scan(const int* __restrict__ deg,
                                               int* __restrict__ off,
                                               int* __restrict__ cursor) {
    __shared__ int ssum[1024];
    int tid = threadIdx.x;
    int base = tid * 32;
    int loc[32];
    int s = 0;
#pragma unroll
    for (int i = 0; i < 32; i++) { loc[i] = s; s += deg[base + i]; }
    ssum[tid] = s;
    __syncthreads();
    for (int ofs = 1; ofs < 1024; ofs <<= 1) {
        int v = (tid >= ofs) ? ssum[tid - ofs] : 0;
        __syncthreads();
        ssum[tid] += v;
        __syncthreads();
    }
    int pre = (tid == 0) ? 0 : ssum[tid - 1];
#pragma unroll
    for (int i = 0; i < 32; i++) { off[base + i] = pre + loc[i]; cursor[base + i] = 0; }
    if (tid == 1023) off[N_NODES] = ssum[1023];
}

__global__ void k_fill(const int* __restrict__ src, const int* __restrict__ dst,
                       const float* __restrict__ dinv, const int* __restrict__ off,
                       int* __restrict__ cursor, int* __restrict__ csrc,
                       float* __restrict__ ccoef, int E) {
    int e = blockIdx.x * 256 + threadIdx.x;
    if (e >= E) return;
    int s = src[e], d = dst[e];
    int p = atomicAdd(&cursor[d], 1);
    int slot = off[d] + p;
    csrc[slot] = s;
    ccoef[slot] = dinv[s] * dinv[d];
}

// ---------------- CSR gather: out = relu( sum_in t[src]*coef + t[n]*dinv^2 + bias )
__global__ void __launch_bounds__(256) k_gather(
    const float* __restrict__ t, const int* __restrict__ csrc,
    const float* __restrict__ ccoef, const int* __restrict__ off,
    const float* __restrict__ dinv, const float* __restrict__ bias,
    float* __restrict__ out) {
    int w = threadIdx.x >> 5, lane = threadIdx.x & 31;
    int n = blockIdx.x * 2 + (w >> 2);
    int chunk = w & 3;
    int c4 = chunk * 32 + lane;   // float4 column index 0..127
    float di = dinv[n];
    float sc = di * di;
    float4 v = ((const float4*)(t + (size_t)n * HID))[c4];
    float4 acc = {v.x * sc, v.y * sc, v.z * sc, v.w * sc};
    int j0 = off[n], j1 = off[n + 1];
#pragma unroll 2
    for (int j = j0; j < j1; j++) {
        int s = __ldg(&csrc[j]);
        float cf = __ldg(&ccoef[j]);
        float4 u = ((const float4*)(t + (size_t)s * HID))[c4];
        acc.x += u.x * cf; acc.y += u.y * cf; acc.z += u.z * cf; acc.w += u.w * cf;
    }
    float4 bb = ((const float4*)bias)[c4];
    float4 o = {fmaxf(acc.x + bb.x, 0.f), fmaxf(acc.y + bb.y, 0.f),
                fmaxf(acc.z + bb.z, 0.f), fmaxf(acc.w + bb.w, 0.f)};
    ((float4*)(out + (size_t)n * HID))[c4] = o;
}

// ---------------- tiled SGEMM, 128x64 block tile, 8x4 per thread, f32x2 ----------------
// EMBED: A row m is emb[x[m]]. Row base: row0 = blockIdx.y * rmul + radd
// (rmul=128,radd=0 for dense; rmul=512,radd=c*128 for gi t-window chunks).
#define ASTRIDE 132
#define BSTRIDE 68
template<bool TRANSB, bool ADD_BIAS, bool EMBED>
__global__ void __launch_bounds__(256) sgemm_kernel(
    const float* __restrict__ A, const float* __restrict__ B,
    const float* __restrict__ bias, float* __restrict__ C,
    int M, int N, int K, const int* __restrict__ xidx, int rmul, int radd) {
    __shared__ float As[16][ASTRIDE];
    __shared__ float Bs[16][BSTRIDE];
    int tid = threadIdx.x;
    int tx = tid & 15, ty = tid >> 4;
    int row0 = blockIdx.y * rmul + radd;
    int col0 = blockIdx.x * 64;
    unsigned long long acc[8][2];
#pragma unroll
    for (int i = 0; i < 8; i++) { acc[i][0] = 0ull; acc[i][1] = 0ull; }

    // resolve A row base pointers once (indirected through x if EMBED)
    const float* arow[2];
#pragma unroll
    for (int i = 0; i < 2; i++) {
        int m = (tid + i * 256) >> 2;
        int r = row0 + m;
        arow[i] = EMBED ? (A + (size_t)__ldg(&xidx[r]) * K) : (A + (size_t)r * K);
    }

    for (int kk = 0; kk < K; kk += 16) {
#pragma unroll
        for (int i = 0; i < 2; i++) {
            int idx = tid + i * 256;
            int m = idx >> 2, kq = idx & 3;
            float4 v = *(const float4*)(arow[i] + kk + kq * 4);
            As[kq * 4 + 0][m] = v.x; As[kq * 4 + 1][m] = v.y;
            As[kq * 4 + 2][m] = v.z; As[kq * 4 + 3][m] = v.w;
        }
        if (TRANSB) {
            int n = tid >> 2, kq = tid & 3;
            float4 v = *(const float4*)(B + (size_t)(col0 + n) * K + kk + kq * 4);
            Bs[kq * 4 + 0][n] = v.x; Bs[kq * 4 + 1][n] = v.y;
            Bs[kq * 4 + 2][n] = v.z; Bs[kq * 4 + 3][n] = v.w;
        } else {
            int k = tid >> 4, n4 = tid & 15;
            float4 v = *(const float4*)(B + (size_t)(kk + k) * N + col0 + n4 * 4);
            *(float4*)&Bs[k][n4 * 4] = v;
        }
        __syncthreads();
#pragma unroll
        for (int k = 0; k < 16; k++) {
            float4 alo = *(const float4*)&As[k][ty * 8];
            float4 ahi = *(const float4*)&As[k][ty * 8 + 4];
            ulonglong2 b2 = *(const ulonglong2*)&Bs[k][tx * 4];
            unsigned long long s0, s1, s2, s3, s4, s5, s6, s7;
            SPLAT2(s0, alo.x); SPLAT2(s1, alo.y); SPLAT2(s2, alo.z); SPLAT2(s3, alo.w);
            SPLAT2(s4, ahi.x); SPLAT2(s5, ahi.y); SPLAT2(s6, ahi.z); SPLAT2(s7, ahi.w);
            FMA2(acc[0][0], s0, b2.x, acc[0][0]); FMA2(acc[0][1], s0, b2.y, acc[0][1]);
            FMA2(acc[1][0], s1, b2.x, acc[1][0]); FMA2(acc[1][1], s1, b2.y, acc[1][1]);
            FMA2(acc[2][0], s2, b2.x, acc[2][0]); FMA2(acc[2][1], s2, b2.y, acc[2][1]);
            FMA2(acc[3][0], s3, b2.x, acc[3][0]); FMA2(acc[3][1], s3, b2.y, acc[3][1]);
            FMA2(acc[4][0], s4, b2.x, acc[4][0]); FMA2(acc[4][1], s4, b2.y, acc[4][1]);
            FMA2(acc[5][0], s5, b2.x, acc[5][0]); FMA2(acc[5][1], s5, b2.y, acc[5][1]);
            FMA2(acc[6][0], s6, b2.x, acc[6][0]); FMA2(acc[6][1], s6, b2.y, acc[6][1]);
            FMA2(acc[7][0], s7, b2.x, acc[7][0]); FMA2(acc[7][1], s7, b2.y, acc[7][1]);
        }
        __syncthreads();
    }
    float4 bb = {0, 0, 0, 0};
    if (ADD_BIAS) bb = *(const float4*)(bias + col0 + (tx << 2));
#pragma unroll
    for (int i = 0; i < 8; i++) {
        float2 lo = *(float2*)&acc[i][0];
        float2 hi = *(float2*)&acc[i][1];
        float4 o = {lo.x + bb.x, lo.y + bb.y, hi.x + bb.z, hi.y + bb.w};
        *(float4*)(C + (size_t)(row0 + ty * 8 + i) * N + col0 + (tx << 2)) = o;
    }
}

__global__ void k_setflag(int* f) { st_release_gpu(f, 1); }
__global__ void k_clrflags(int* f) { f[threadIdx.x * 32] = 0; }

// ---------------- persistent GRU: 8 graph-groups x 16 col-blocks (R13) ----------------
// Adds one acquire-poll per 128-step window on the gi chunk flags (chunks 1-3
// are produced concurrently on the GRU-free SMs).
#define GROW    129                     // float4 stride per smem row
#define REDS    13                      // floats per reduction slot row
#define GRU_SMEM ((8 + 96) * GROW * 16 + 4 * 64 * REDS * 4)   // 227968 B

__device__ __forceinline__ float sigmoidf_(float x) { return 1.0f / (1.0f + __expf(-x)); }

__global__ void __launch_bounds__(256, 1) k_gru_all(
    const float* __restrict__ gi, const float* __restrict__ Whh,
    const float* __restrict__ bhh, float* __restrict__ hsum,
    float* __restrict__ hbuf0, float* __restrict__ hbuf1, int* bar,
    const int* __restrict__ giprog) {
    extern __shared__ float4 sm4[];
    float4* hs = sm4;                    // [8][GROW]
    float4* ws = sm4 + 8 * GROW;         // [96][GROW]  row = c*3+gate
    float*  red = (float*)(sm4 + 104 * GROW);   // [4*64][REDS]
    int tid = threadIdx.x;
    int bk = blockIdx.x;
    int grp = bk >> 4;                   // graph group 0..7
    int cg  = bk & 15;                   // col block 0..15
    int col0 = cg * 32;
    int g0 = grp * 8;
    int* gbar = bar + grp * 32;

    // load Whh slab once: ws[c*3+gate][k4] = Whh[gate*HID + col0 + c][k4]
#pragma unroll
    for (int i = 0; i < 48; i++) {
        int idx = tid + i * 256;           // 0..12287
        int r = idx >> 7, k4 = idx & 127;  // r 0..95
        int c = r / 3, gate = r - c * 3;
        ws[r * GROW + k4] =
            __ldg((const float4*)Whh + (size_t)(gate * HID + col0 + c) * 128 + k4);
    }

    // compute-phase identity (R10)
    int kg = tid >> 6;                  // k-group 0..3
    int worker = tid & 63;
    int wc = worker >> 1;               // col 0..31
    int gq = worker & 1;                // graph parity: graphs gq+2i
    int kbase = kg * 32;
    const ulonglong2* hp0 = (const ulonglong2*)(hs + (gq + 0) * GROW);
    const ulonglong2* hp1 = (const ulonglong2*)(hs + (gq + 2) * GROW);
    const ulonglong2* hp2 = (const ulonglong2*)(hs + (gq + 4) * GROW);
    const ulonglong2* hp3 = (const ulonglong2*)(hs + (gq + 6) * GROW);
    const ulonglong2* wrp = (const ulonglong2*)(ws + (wc * 3 + 0) * GROW);
    const ulonglong2* wzp = (const ulonglong2*)(ws + (wc * 3 + 1) * GROW);
    const ulonglong2* wnp = (const ulonglong2*)(ws + (wc * 3 + 2) * GROW);
    float* myred = red + (kg * 64 + worker) * REDS;

    // gate-phase identity: thread = (c2 0..31, g2 0..7), one output per gate
    int g2 = tid & 7, c2 = tid >> 3;
    int col = col0 + c2;
    int gg  = g0 + g2;
    int worker2 = c2 * 2 + (g2 & 1);    // worker holding (g2, c2)
    int ii = g2 >> 1;                   // register index within that worker
    float bh_r = bhh[col], bh_z = bhh[HID + col], bh_n = bhh[2 * HID + col];
    const float* girow = gi + (size_t)gg * LSEQ * GI3 + col;
    float hsum_acc = 0.0f;
    __syncthreads();

    for (int t = 0; t < LSEQ; t++) {
        const float* hb = (t & 1) ? hbuf1 : hbuf0;
        float*       hn = (t & 1) ? hbuf0 : hbuf1;

        // wait for this t-window's gi chunk (chunks 1-3 computed concurrently)
        if ((t & 127) == 0 && t != 0) {
            const int* fp = giprog + ((t >> 7) - 1) * 32;
            while (ld_acquire_gpu(fp) == 0) { }
        }

        // prefetch gate inputs for this step (streaming, read-once)
        const float* gp = girow + (size_t)t * GI3;
        float gir = __ldcs(gp);
        float giz = __ldcs(gp + HID);
        float gin = __ldcs(gp + 2 * HID);

        // stage this group's 8 graphs of h (16 KB), bypass L1
        const float4* hb4 = (const float4*)(hb + (size_t)g0 * HID);
#pragma unroll
        for (int i = 0; i < 4; i++) {
            int idx = tid + i * 256;            // 0..1023
            hs[(idx >> 7) * GROW + (idx & 127)] = __ldcg(hb4 + idx);
        }
        __syncthreads();

        float hold = ((const float*)(hs + g2 * GROW))[col];

        // 12 partial dots over this k-group (pairwise f32x2)
        unsigned long long a0[4], a1[4], a2[4];
#pragma unroll
        for (int i = 0; i < 4; i++) { a0[i] = 0ull; a1[i] = 0ull; a2[i] = 0ull; }
#pragma unroll 8
        for (int kk = 0; kk < 32; kk++) {
            int k4 = kbase + kk;
            ulonglong2 h0 = hp0[k4], h1 = hp1[k4], h2 = hp2[k4], h3 = hp3[k4];
            ulonglong2 wr = wrp[k4], wz = wzp[k4], wn = wnp[k4];
            FMA2(a0[0], h0.x, wr.x, a0[0]); FMA2(a0[0], h0.y, wr.y, a0[0]);
            FMA2(a0[1], h1.x, wr.x, a0[1]); FMA2(a0[1], h1.y, wr.y, a0[1]);
            FMA2(a0[2], h2.x, wr.x, a0[2]); FMA2(a0[2], h2.y, wr.y, a0[2]);
            FMA2(a0[3], h3.x, wr.x, a0[3]); FMA2(a0[3], h3.y, wr.y, a0[3]);
            FMA2(a1[0], h0.x, wz.x, a1[0]); FMA2(a1[0], h0.y, wz.y, a1[0]);
            FMA2(a1[1], h1.x, wz.x, a1[1]); FMA2(a1[1], h1.y, wz.y, a1[1]);
            FMA2(a1[2], h2.x, wz.x, a1[2]); FMA2(a1[2], h2.y, wz.y, a1[2]);
            FMA2(a1[3], h3.x, wz.x, a1[3]); FMA2(a1[3], h3.y, wz.y, a1[3]);
            FMA2(a2[0], h0.x, wn.x, a2[0]); FMA2(a2[0], h0.y, wn.y, a2[0]);
            FMA2(a2[1], h1.x, wn.x, a2[1]); FMA2(a2[1], h1.y, wn.y, a2[1]);
            FMA2(a2[2], h2.x, wn.x, a2[2]); FMA2(a2[2], h2.y, wn.y, a2[2]);
            FMA2(a2[3], h3.x, wn.x, a2[3]); FMA2(a2[3], h3.y, wn.y, a2[3]);
        }
#pragma unroll
        for (int i = 0; i < 4; i++) {
            float2 f;
            f = *(float2*)&a0[i]; myred[0 + i] = f.x + f.y;
            f = *(float2*)&a1[i]; myred[4 + i] = f.x + f.y;
            f = *(float2*)&a2[i]; myred[8 + i] = f.x + f.y;
        }
        __syncthreads();

        // reduce across 4 k-groups + gates + state update
        float s0 = 0, s1 = 0, s2 = 0;
#pragma unroll
        for (int q = 0; q < 4; q++) {
            const float* rp = red + (q * 64 + worker2) * REDS + ii;
            s0 += rp[0]; s1 += rp[4]; s2 += rp[8];
        }
        float r  = sigmoidf_(gir + s0 + bh_r);
        float z  = sigmoidf_(giz + s1 + bh_z);
        float nn = tanhf(gin + r * (s2 + bh_n));
        float hnew = (1.0f - z) * nn + z * hold;
        __stcg(hn + (size_t)gg * HID + col, hnew);
        hsum_acc += hnew;

        // release/acquire group barrier (16 blocks): no membar, no extra sync
        __syncthreads();
        if (tid == 0) red_release_gpu(gbar, 1);
        int target = 16 * (t + 1);
        while (ld_acquire_gpu(gbar) < target) { }
    }
    hsum[(size_t)gg * HID + col] = hsum_acc;
}

// ---------------- head ----------------
__global__ void __launch_bounds__(512) k_head(
    const float* __restrict__ hsum, const float* __restrict__ focal,
    const float* __restrict__ fc1w, const float* __restrict__ fc1b,
    const float* __restrict__ fc2w, const float* __restrict__ fc2b,
    float* __restrict__ out) {
    __shared__ float g[HID + 1];
    __shared__ float red[HID];
    int b = blockIdx.x, j = threadIdx.x;
    g[j] = hsum[b * HID + j] * (1.0f / (float)LSEQ);
    if (j == 0) g[HID] = focal[b];
    __syncthreads();
    float acc = fc1b[j];
    for (int k = 0; k < HID + 1; k++) acc += g[k] * fc1w[(size_t)k * HID + j];
    float a = fmaxf(acc, 0.0f);
    red[j] = a * fc2w[j];
    __syncthreads();
    for (int s = 256; s > 0; s >>= 1) {
        if (j < s) red[j] += red[j + s];
        __syncthreads();
    }
    if (j == 0) out[b] = sigmoidf_(red[0] + fc2b[0]);
}

// ---------------- launch ----------------
extern "C" void kernel_launch(void* const* d_in, const int* in_sizes, int n_in,
                              void* d_out, int out_size) {
    const int*   x     = (const int*)  d_in[0];
    const int*   edge  = (const int*)  d_in[1];
    const float* focal = (const float*)d_in[3];
    const float* emb   = (const float*)d_in[4];
    const float* W1    = (const float*)d_in[5];
    const float* b1    = (const float*)d_in[6];
    const float* W2    = (const float*)d_in[7];
    const float* b2    = (const float*)d_in[8];
    const float* Wih   = (const float*)d_in[9];
    const float* Whh   = (const float*)d_in[10];
    const float* bih   = (const float*)d_in[11];
    const float* bhh   = (const float*)d_in[12];
    const float* fc1w  = (const float*)d_in[13];
    const float* fc1b  = (const float*)d_in[14];
    const float* fc2w  = (const float*)d_in[15];
    const float* fc2b  = (const float*)d_in[16];
    int E = in_sizes[1] / 2;
    const int* src = edge;
    const int* dst = edge + E;

    float *t, *h1, *h2, *gi, *dinv, *hbuf, *hsum, *ccoef;
    int *deg, *off, *cursor, *csrc, *bar, *giprog;
    cudaGetSymbolAddress((void**)&t,     g_t);
    cudaGetSymbolAddress((void**)&h1,    g_h1);
    cudaGetSymbolAddress((void**)&h2,    g_h2);
    cudaGetSymbolAddress((void**)&gi,    g_gi);
    cudaGetSymbolAddress((void**)&deg,   g_deg);
    cudaGetSymbolAddress((void**)&dinv,  g_dinv);
    cudaGetSymbolAddress((void**)&off,   g_off);
    cudaGetSymbolAddress((void**)&cursor,g_cursor);
    cudaGetSymbolAddress((void**)&csrc,  g_csrc);
    cudaGetSymbolAddress((void**)&ccoef, g_ccoef);
    cudaGetSymbolAddress((void**)&hbuf,  g_hbuf);
    cudaGetSymbolAddress((void**)&hsum,  g_hsum);
    cudaGetSymbolAddress((void**)&bar,   g_bar);
    cudaGetSymbolAddress((void**)&giprog,g_giprog);

    cudaFuncSetAttribute(k_gru_all, cudaFuncAttributeMaxDynamicSharedMemorySize, GRU_SMEM);

    // lazily-created side stream + events (host objects only; deterministic work)
    static cudaStream_t s2 = nullptr;
    static cudaEvent_t evA = nullptr, evB = nullptr;
    if (!s2) {
        cudaStreamCreateWithFlags(&s2, cudaStreamNonBlocking);
        cudaEventCreateWithFlags(&evA, cudaEventDisableTiming);
        cudaEventCreateWithFlags(&evB, cudaEventDisableTiming);
    }

    // CSR build (graph fixed for both layers)
    cudaMemsetAsync(deg, 0, N_NODES * sizeof(int), 0);
    k_count<<<(E + 255) / 256, 256>>>(dst, deg, E);
    k_dinv<<<N_NODES / 256, 256>>>(deg, dinv);
    k_scan<<<1, 1024>>>(deg, off, cursor);
    k_fill<<<(E + 255) / 256, 256>>>(src, dst, dinv, off, cursor, csrc, ccoef, E);

    // GCN layer 1 (embedding gather fused into the GEMM A-load)
    sgemm_kernel<false, false, true><<<dim3(HID / 64, N_NODES / 128), 256>>>(
        emb, W1, nullptr, t, N_NODES, HID, DIM, x, 128, 0);
    k_gather<<<N_NODES / 2, 256>>>(t, csrc, ccoef, off, dinv, b1, h1);

    // GCN layer 2
    sgemm_kernel<false, false, false><<<dim3(HID / 64, N_NODES / 128), 256>>>(
        h1, W2, nullptr, t, N_NODES, HID, HID, nullptr, 128, 0);
    k_gather<<<N_NODES / 2, 256>>>(t, csrc, ccoef, off, dinv, b2, h2);

    // reset gi progress flags, then fork side stream (h2 ready here)
    k_clrflags<<<1, 3>>>(giprog);
    cudaEventRecord(evA, 0);
    cudaStreamWaitEvent(s2, evA, 0);

    // gi chunk 0 (t in [0,128)) on main stream before the GRU
    sgemm_kernel<true, true, false><<<dim3(GI3 / 64, NB), 256>>>(
        h2, Wih, bih, gi, N_NODES, GI3, HID, nullptr, 512, 0);

    // gi chunks 1-3 on side stream, concurrent with the GRU (20 free SMs)
    for (int c = 1; c < 4; c++) {
        sgemm_kernel<true, true, false><<<dim3(GI3 / 64, NB), 256, 0, s2>>>(
            h2, Wih, bih, gi, N_NODES, GI3, HID, nullptr, 512, c * 128);
        k_setflag<<<1, 1, 0, s2>>>(giprog + (c - 1) * 32);
    }
    cudaEventRecord(evB, s2);

    // persistent GRU
    cudaMemsetAsync(hbuf, 0, NB * HID * sizeof(float), 0);   // hbuf[0] = h_0 = 0
    cudaMemsetAsync(bar, 0, 8 * 32 * sizeof(int), 0);
    k_gru_all<<<128, 256, GRU_SMEM>>>(gi, Whh, bhh, hsum, hbuf, hbuf + NB * HID,
                                      bar, giprog);

    // join side stream, then head
    cudaStreamWaitEvent(0, evB, 0);
    k_head<<<NB, 512>>>(hsum, focal, fc1w, fc1b, fc2w, fc2b, (float*)d_out);
}

// round 17
// speedup vs baseline: 1.3212x; 1.3212x over previous
#include <cuda_runtime.h>
#include <math.h>
#include <stdint.h>

// Problem constants (fixed by setup_inputs)
#define N_NODES 32768
#define NB      64
#define LSEQ    512
#define DIM     256
#define HID     512
#define GI3     1536   // 3*HID
#define EDGES   524288

// ---------------- f32x2 packed math (sm_103a) ----------------
#define FMA2(d, a, b, c) \
    asm("fma.rn.f32x2 %0, %1, %2, %3;" : "=l"(d) : "l"(a), "l"(b), "l"(c))
#define SPLAT2(d, s) \
    asm("mov.b64 %0, {%1, %2};" : "=l"(d) : "f"(s), "f"(s))

__device__ __forceinline__ int ld_acquire_gpu(const int* p) {
    int v;
    asm volatile("ld.global.acquire.gpu.b32 %0, [%1];" : "=r"(v) : "l"(p) : "memory");
    return v;
}
__device__ __forceinline__ void red_release_gpu(int* p, int v) {
    asm volatile("red.global.add.release.gpu.s32 [%0], %1;" :: "l"(p), "r"(v) : "memory");
}

// ---------------- scratch (static device globals; no allocation) ----------------
__device__ float g_t  [(size_t)N_NODES * HID];
__device__ float g_h1 [(size_t)N_NODES * HID];
__device__ float g_h2 [(size_t)N_NODES * HID];
__device__ float g_gi [(size_t)N_NODES * GI3];
__device__ int   g_deg [N_NODES];
__device__ float g_dinv[N_NODES];
__device__ int   g_off [N_NODES + 1];
__device__ int   g_cursor[N_NODES];
__device__ int   g_csrc[EDGES];
__device__ float g_ccoef[EDGES];
__device__ float g_hbuf[2][NB * HID];
__device__ float g_hsum[NB * HID];
__device__ int   g_bar[8 * 32];   // one counter per graph-group, separate 128B lines

// ---------------- degree / CSR build ----------------
__global__ void k_count(const int* __restrict__ dst, int* __restrict__ deg, int E) {
    int i = blockIdx.x * 256 + threadIdx.x;
    if (i < E) atomicAdd(&deg[dst[i]], 1);
}

__global__ void k_dinv(const int* __restrict__ deg, float* __restrict__ dinv) {
    int i = blockIdx.x * 256 + threadIdx.x;
    if (i < N_NODES) dinv[i] = rsqrtf((float)(deg[i] + 1));  // +1 self loop
}

__global__ void __launch_bounds__(1024) k_scan(const int* __restrict__ deg,
                                               int* __restrict__ off,
                                               int* __restrict__ cursor) {
    __shared__ int ssum[1024];
    int tid = threadIdx.x;
    int base = tid * 32;
    int loc[32];
    int s = 0;
#pragma unroll
    for (int i = 0; i < 32; i++) { loc[i] = s; s += deg[base + i]; }
    ssum[tid] = s;
    __syncthreads();
    for (int ofs = 1; ofs < 1024; ofs <<= 1) {
        int v = (tid >= ofs) ? ssum[tid - ofs] : 0;
        __syncthreads();
        ssum[tid] += v;
        __syncthreads();
    }
    int pre = (tid == 0) ? 0 : ssum[tid - 1];
#pragma unroll
    for (int i = 0; i < 32; i++) { off[base + i] = pre + loc[i]; cursor[base + i] = 0; }
    if (tid == 1023) off[N_NODES] = ssum[1023];
}

__global__ void k_fill(const int* __restrict__ src, const int* __restrict__ dst,
                       const float* __restrict__ dinv, const int* __restrict__ off,
                       int* __restrict__ cursor, int* __restrict__ csrc,
                       float* __restrict__ ccoef, int E) {
    int e = blockIdx.x * 256 + threadIdx.x;
    if (e >= E) return;
    int s = src[e], d = dst[e];
    int p = atomicAdd(&cursor[d], 1);
    int slot = off[d] + p;
    csrc[slot] = s;
    ccoef[slot] = dinv[s] * dinv[d];
}

// ---------------- CSR gather: out = relu( sum_in t[src]*coef + t[n]*dinv^2 + bias )
__global__ void __launch_bounds__(256) k_gather(
    const float* __restrict__ t, const int* __restrict__ csrc,
    const float* __restrict__ ccoef, const int* __restrict__ off,
    const float* __restrict__ dinv, const float* __restrict__ bias,
    float* __restrict__ out) {
    int w = threadIdx.x >> 5, lane = threadIdx.x & 31;
    int n = blockIdx.x * 2 + (w >> 2);
    int chunk = w & 3;
    int c4 = chunk * 32 + lane;   // float4 column index 0..127
    float di = dinv[n];
    float sc = di * di;
    float4 v = ((const float4*)(t + (size_t)n * HID))[c4];
    float4 acc = {v.x * sc, v.y * sc, v.z * sc, v.w * sc};
    int j0 = off[n], j1 = off[n + 1];
#pragma unroll 2
    for (int j = j0; j < j1; j++) {
        int s = __ldg(&csrc[j]);
        float cf = __ldg(&ccoef[j]);
        float4 u = ((const float4*)(t + (size_t)s * HID))[c4];
        acc.x += u.x * cf; acc.y += u.y * cf; acc.z += u.z * cf; acc.w += u.w * cf;
    }
    float4 bb = ((const float4*)bias)[c4];
    float4 o = {fmaxf(acc.x + bb.x, 0.f), fmaxf(acc.y + bb.y, 0.f),
                fmaxf(acc.z + bb.z, 0.f), fmaxf(acc.w + bb.w, 0.f)};
    ((float4*)(out + (size_t)n * HID))[c4] = o;
}

// ---------------- tiled SGEMM, 128x64 block tile, 8x4 per thread, f32x2 ----------------
// EMBED: A row m is emb[x[m]] (fused embedding gather; x indices resolved once).
#define ASTRIDE 132
#define BSTRIDE 68
template<bool TRANSB, bool ADD_BIAS, bool EMBED>
__global__ void __launch_bounds__(256) sgemm_kernel(
    const float* __restrict__ A, const float* __restrict__ B,
    const float* __restrict__ bias, float* __restrict__ C,
    int M, int N, int K, const int* __restrict__ xidx) {
    __shared__ float As[16][ASTRIDE];
    __shared__ float Bs[16][BSTRIDE];
    int tid = threadIdx.x;
    int tx = tid & 15, ty = tid >> 4;
    int row0 = blockIdx.y * 128;
    int col0 = blockIdx.x * 64;
    unsigned long long acc[8][2];
#pragma unroll
    for (int i = 0; i < 8; i++) { acc[i][0] = 0ull; acc[i][1] = 0ull; }

    // resolve A row base pointers once (indirected through x if EMBED)
    const float* arow[2];
#pragma unroll
    for (int i = 0; i < 2; i++) {
        int m = (tid + i * 256) >> 2;
        int r = row0 + m;
        arow[i] = EMBED ? (A + (size_t)__ldg(&xidx[r]) * K) : (A + (size_t)r * K);
    }

    for (int kk = 0; kk < K; kk += 16) {
#pragma unroll
        for (int i = 0; i < 2; i++) {
            int idx = tid + i * 256;
            int m = idx >> 2, kq = idx & 3;
            float4 v = *(const float4*)(arow[i] + kk + kq * 4);
            As[kq * 4 + 0][m] = v.x; As[kq * 4 + 1][m] = v.y;
            As[kq * 4 + 2][m] = v.z; As[kq * 4 + 3][m] = v.w;
        }
        if (TRANSB) {
            int n = tid >> 2, kq = tid & 3;
            float4 v = *(const float4*)(B + (size_t)(col0 + n) * K + kk + kq * 4);
            Bs[kq * 4 + 0][n] = v.x; Bs[kq * 4 + 1][n] = v.y;
            Bs[kq * 4 + 2][n] = v.z; Bs[kq * 4 + 3][n] = v.w;
        } else {
            int k = tid >> 4, n4 = tid & 15;
            float4 v = *(const float4*)(B + (size_t)(kk + k) * N + col0 + n4 * 4);
            *(float4*)&Bs[k][n4 * 4] = v;
        }
        __syncthreads();
#pragma unroll
        for (int k = 0; k < 16; k++) {
            float4 alo = *(const float4*)&As[k][ty * 8];
            float4 ahi = *(const float4*)&As[k][ty * 8 + 4];
            ulonglong2 b2 = *(const ulonglong2*)&Bs[k][tx * 4];
            unsigned long long s0, s1, s2, s3, s4, s5, s6, s7;
            SPLAT2(s0, alo.x); SPLAT2(s1, alo.y); SPLAT2(s2, alo.z); SPLAT2(s3, alo.w);
            SPLAT2(s4, ahi.x); SPLAT2(s5, ahi.y); SPLAT2(s6, ahi.z); SPLAT2(s7, ahi.w);
            FMA2(acc[0][0], s0, b2.x, acc[0][0]); FMA2(acc[0][1], s0, b2.y, acc[0][1]);
            FMA2(acc[1][0], s1, b2.x, acc[1][0]); FMA2(acc[1][1], s1, b2.y, acc[1][1]);
            FMA2(acc[2][0], s2, b2.x, acc[2][0]); FMA2(acc[2][1], s2, b2.y, acc[2][1]);
            FMA2(acc[3][0], s3, b2.x, acc[3][0]); FMA2(acc[3][1], s3, b2.y, acc[3][1]);
            FMA2(acc[4][0], s4, b2.x, acc[4][0]); FMA2(acc[4][1], s4, b2.y, acc[4][1]);
            FMA2(acc[5][0], s5, b2.x, acc[5][0]); FMA2(acc[5][1], s5, b2.y, acc[5][1]);
            FMA2(acc[6][0], s6, b2.x, acc[6][0]); FMA2(acc[6][1], s6, b2.y, acc[6][1]);
            FMA2(acc[7][0], s7, b2.x, acc[7][0]); FMA2(acc[7][1], s7, b2.y, acc[7][1]);
        }
        __syncthreads();
    }
    float4 bb = {0, 0, 0, 0};
    if (ADD_BIAS) bb = *(const float4*)(bias + col0 + (tx << 2));
#pragma unroll
    for (int i = 0; i < 8; i++) {
        float2 lo = *(float2*)&acc[i][0];
        float2 hi = *(float2*)&acc[i][1];
        float4 o = {lo.x + bb.x, lo.y + bb.y, hi.x + bb.z, hi.y + bb.w};
        *(float4*)(C + (size_t)(row0 + ty * 8 + i) * N + col0 + (tx << 2)) = o;
    }
}

// ---------------- persistent GRU: 8 graph-groups x 16 col-blocks (R13) ----------------
#define GROW    129                     // float4 stride per smem row
#define REDS    13                      // floats per reduction slot row
#define GRU_SMEM ((8 + 96) * GROW * 16 + 4 * 64 * REDS * 4)   // 227968 B

__device__ __forceinline__ float sigmoidf_(float x) { return 1.0f / (1.0f + __expf(-x)); }

__global__ void __launch_bounds__(256, 1) k_gru_all(
    const float* __restrict__ gi, const float* __restrict__ Whh,
    const float* __restrict__ bhh, float* __restrict__ hsum,
    float* __restrict__ hbuf0, float* __restrict__ hbuf1, int* bar) {
    extern __shared__ float4 sm4[];
    float4* hs = sm4;                    // [8][GROW]
    float4* ws = sm4 + 8 * GROW;         // [96][GROW]  row = c*3+gate
    float*  red = (float*)(sm4 + 104 * GROW);   // [4*64][REDS]
    int tid = threadIdx.x;
    int bk = blockIdx.x;
    int grp = bk >> 4;                   // graph group 0..7
    int cg  = bk & 15;                   // col block 0..15
    int col0 = cg * 32;
    int g0 = grp * 8;
    int* gbar = bar + grp * 32;

    // load Whh slab once: ws[c*3+gate][k4] = Whh[gate*HID + col0 + c][k4]
#pragma unroll
    for (int i = 0; i < 48; i++) {
        int idx = tid + i * 256;           // 0..12287
        int r = idx >> 7, k4 = idx & 127;  // r 0..95
        int c = r / 3, gate = r - c * 3;
        ws[r * GROW + k4] =
            __ldg((const float4*)Whh + (size_t)(gate * HID + col0 + c) * 128 + k4);
    }

    // compute-phase identity (R10)
    int kg = tid >> 6;                  // k-group 0..3
    int worker = tid & 63;
    int wc = worker >> 1;               // col 0..31
    int gq = worker & 1;                // graph parity: graphs gq+2i
    int kbase = kg * 32;
    const ulonglong2* hp0 = (const ulonglong2*)(hs + (gq + 0) * GROW);
    const ulonglong2* hp1 = (const ulonglong2*)(hs + (gq + 2) * GROW);
    const ulonglong2* hp2 = (const ulonglong2*)(hs + (gq + 4) * GROW);
    const ulonglong2* hp3 = (const ulonglong2*)(hs + (gq + 6) * GROW);
    const ulonglong2* wrp = (const ulonglong2*)(ws + (wc * 3 + 0) * GROW);
    const ulonglong2* wzp = (const ulonglong2*)(ws + (wc * 3 + 1) * GROW);
    const ulonglong2* wnp = (const ulonglong2*)(ws + (wc * 3 + 2) * GROW);
    float* myred = red + (kg * 64 + worker) * REDS;

    // gate-phase identity: thread = (c2 0..31, g2 0..7), one output per gate
    int g2 = tid & 7, c2 = tid >> 3;
    int col = col0 + c2;
    int gg  = g0 + g2;
    int worker2 = c2 * 2 + (g2 & 1);    // worker holding (g2, c2)
    int ii = g2 >> 1;                   // register index within that worker
    float bh_r = bhh[col], bh_z = bhh[HID + col], bh_n = bhh[2 * HID + col];
    const float* girow = gi + (size_t)gg * LSEQ * GI3 + col;
    float hsum_acc = 0.0f;
    __syncthreads();

    for (int t = 0; t < LSEQ; t++) {
        const float* hb = (t & 1) ? hbuf1 : hbuf0;
        float*       hn = (t & 1) ? hbuf0 : hbuf1;

        // prefetch gate inputs for this step (streaming, read-once)
        const float* gp = girow + (size_t)t * GI3;
        float gir = __ldcs(gp);
        float giz = __ldcs(gp + HID);
        float gin = __ldcs(gp + 2 * HID);

        // stage this group's 8 graphs of h (16 KB), bypass L1
        const float4* hb4 = (const float4*)(hb + (size_t)g0 * HID);
#pragma unroll
        for (int i = 0; i < 4; i++) {
            int idx = tid + i * 256;            // 0..1023
            hs[(idx >> 7) * GROW + (idx & 127)] = __ldcg(hb4 + idx);
        }
        __syncthreads();

        float hold = ((const float*)(hs + g2 * GROW))[col];

        // 12 partial dots over this k-group (pairwise f32x2)
        unsigned long long a0[4], a1[4], a2[4];
#pragma unroll
        for (int i = 0; i < 4; i++) { a0[i] = 0ull; a1[i] = 0ull; a2[i] = 0ull; }
#pragma unroll 8
        for (int kk = 0; kk < 32; kk++) {
            int k4 = kbase + kk;
            ulonglong2 h0 = hp0[k4], h1 = hp1[k4], h2 = hp2[k4], h3 = hp3[k4];
            ulonglong2 wr = wrp[k4], wz = wzp[k4], wn = wnp[k4];
            FMA2(a0[0], h0.x, wr.x, a0[0]); FMA2(a0[0], h0.y, wr.y, a0[0]);
            FMA2(a0[1], h1.x, wr.x, a0[1]); FMA2(a0[1], h1.y, wr.y, a0[1]);
            FMA2(a0[2], h2.x, wr.x, a0[2]); FMA2(a0[2], h2.y, wr.y, a0[2]);
            FMA2(a0[3], h3.x, wr.x, a0[3]); FMA2(a0[3], h3.y, wr.y, a0[3]);
            FMA2(a1[0], h0.x, wz.x, a1[0]); FMA2(a1[0], h0.y, wz.y, a1[0]);
            FMA2(a1[1], h1.x, wz.x, a1[1]); FMA2(a1[1], h1.y, wz.y, a1[1]);
            FMA2(a1[2], h2.x, wz.x, a1[2]); FMA2(a1[2], h2.y, wz.y, a1[2]);
            FMA2(a1[3], h3.x, wz.x, a1[3]); FMA2(a1[3], h3.y, wz.y, a1[3]);
            FMA2(a2[0], h0.x, wn.x, a2[0]); FMA2(a2[0], h0.y, wn.y, a2[0]);
            FMA2(a2[1], h1.x, wn.x, a2[1]); FMA2(a2[1], h1.y, wn.y, a2[1]);
            FMA2(a2[2], h2.x, wn.x, a2[2]); FMA2(a2[2], h2.y, wn.y, a2[2]);
            FMA2(a2[3], h3.x, wn.x, a2[3]); FMA2(a2[3], h3.y, wn.y, a2[3]);
        }
#pragma unroll
        for (int i = 0; i < 4; i++) {
            float2 f;
            f = *(float2*)&a0[i]; myred[0 + i] = f.x + f.y;
            f = *(float2*)&a1[i]; myred[4 + i] = f.x + f.y;
            f = *(float2*)&a2[i]; myred[8 + i] = f.x + f.y;
        }
        __syncthreads();

        // reduce across 4 k-groups + gates + state update
        float s0 = 0, s1 = 0, s2 = 0;
#pragma unroll
        for (int q = 0; q < 4; q++) {
            const float* rp = red + (q * 64 + worker2) * REDS + ii;
            s0 += rp[0]; s1 += rp[4]; s2 += rp[8];
        }
        float r  = sigmoidf_(gir + s0 + bh_r);
        float z  = sigmoidf_(giz + s1 + bh_z);
        float nn = tanhf(gin + r * (s2 + bh_n));
        float hnew = (1.0f - z) * nn + z * hold;
        __stcg(hn + (size_t)gg * HID + col, hnew);
        hsum_acc += hnew;

        // release/acquire group barrier (16 blocks): no membar, no extra sync
        __syncthreads();
        if (tid == 0) red_release_gpu(gbar, 1);
        int target = 16 * (t + 1);
        while (ld_acquire_gpu(gbar) < target) { }
    }
    hsum[(size_t)gg * HID + col] = hsum_acc;
}

// ---------------- head ----------------
__global__ void __launch_bounds__(512) k_head(
    const float* __restrict__ hsum, const float* __restrict__ focal,
    const float* __restrict__ fc1w, const float* __restrict__ fc1b,
    const float* __restrict__ fc2w, const float* __restrict__ fc2b,
    float* __restrict__ out) {
    __shared__ float g[HID + 1];
    __shared__ float red[HID];
    int b = blockIdx.x, j = threadIdx.x;
    g[j] = hsum[b * HID + j] * (1.0f / (float)LSEQ);
    if (j == 0) g[HID] = focal[b];
    __syncthreads();
    float acc = fc1b[j];
    for (int k = 0; k < HID + 1; k++) acc += g[k] * fc1w[(size_t)k * HID + j];
    float a = fmaxf(acc, 0.0f);
    red[j] = a * fc2w[j];
    __syncthreads();
    for (int s = 256; s > 0; s >>= 1) {
        if (j < s) red[j] += red[j + s];
        __syncthreads();
    }
    if (j == 0) out[b] = sigmoidf_(red[0] + fc2b[0]);
}

// ---------------- launch ----------------
extern "C" void kernel_launch(void* const* d_in, const int* in_sizes, int n_in,
                              void* d_out, int out_size) {
    const int*   x     = (const int*)  d_in[0];
    const int*   edge  = (const int*)  d_in[1];
    const float* focal = (const float*)d_in[3];
    const float* emb   = (const float*)d_in[4];
    const float* W1    = (const float*)d_in[5];
    const float* b1    = (const float*)d_in[6];
    const float* W2    = (const float*)d_in[7];
    const float* b2    = (const float*)d_in[8];
    const float* Wih   = (const float*)d_in[9];
    const float* Whh   = (const float*)d_in[10];
    const float* bih   = (const float*)d_in[11];
    const float* bhh   = (const float*)d_in[12];
    const float* fc1w  = (const float*)d_in[13];
    const float* fc1b  = (const float*)d_in[14];
    const float* fc2w  = (const float*)d_in[15];
    const float* fc2b  = (const float*)d_in[16];
    int E = in_sizes[1] / 2;
    const int* src = edge;
    const int* dst = edge + E;

    float *t, *h1, *h2, *gi, *dinv, *hbuf, *hsum, *ccoef;
    int *deg, *off, *cursor, *csrc, *bar;
    cudaGetSymbolAddress((void**)&t,     g_t);
    cudaGetSymbolAddress((void**)&h1,    g_h1);
    cudaGetSymbolAddress((void**)&h2,    g_h2);
    cudaGetSymbolAddress((void**)&gi,    g_gi);
    cudaGetSymbolAddress((void**)&deg,   g_deg);
    cudaGetSymbolAddress((void**)&dinv,  g_dinv);
    cudaGetSymbolAddress((void**)&off,   g_off);
    cudaGetSymbolAddress((void**)&cursor,g_cursor);
    cudaGetSymbolAddress((void**)&csrc,  g_csrc);
    cudaGetSymbolAddress((void**)&ccoef, g_ccoef);
    cudaGetSymbolAddress((void**)&hbuf,  g_hbuf);
    cudaGetSymbolAddress((void**)&hsum,  g_hsum);
    cudaGetSymbolAddress((void**)&bar,   g_bar);

    cudaFuncSetAttribute(k_gru_all, cudaFuncAttributeMaxDynamicSharedMemorySize, GRU_SMEM);

    // lazily-created side stream + events (host objects only)
    static cudaStream_t s2 = nullptr;
    static cudaEvent_t evA = nullptr, evB = nullptr;
    if (!s2) {
        cudaStreamCreateWithFlags(&s2, cudaStreamNonBlocking);
        cudaEventCreateWithFlags(&evA, cudaEventDisableTiming);
        cudaEventCreateWithFlags(&evB, cudaEventDisableTiming);
    }

    // fork: CSR build + GRU-state memsets on side stream, concurrent with GEMM1
    cudaEventRecord(evA, 0);
    cudaStreamWaitEvent(s2, evA, 0);
    cudaMemsetAsync(deg, 0, N_NODES * sizeof(int), s2);
    k_count<<<(E + 255) / 256, 256, 0, s2>>>(dst, deg, E);
    k_dinv<<<N_NODES / 256, 256, 0, s2>>>(deg, dinv);
    k_scan<<<1, 1024, 0, s2>>>(deg, off, cursor);
    k_fill<<<(E + 255) / 256, 256, 0, s2>>>(src, dst, dinv, off, cursor, csrc, ccoef, E);
    cudaMemsetAsync(hbuf, 0, NB * HID * sizeof(float), s2);  // hbuf[0] = h_0 = 0
    cudaMemsetAsync(bar, 0, 8 * 32 * sizeof(int), s2);
    cudaEventRecord(evB, s2);

    // GCN layer 1 GEMM (embedding gather fused into the A-load), concurrent with CSR
    sgemm_kernel<false, false, true><<<dim3(HID / 64, N_NODES / 128), 256>>>(
        emb, W1, nullptr, t, N_NODES, HID, DIM, x);

    // join before the gather (needs CSR)
    cudaStreamWaitEvent(0, evB, 0);
    k_gather<<<N_NODES / 2, 256>>>(t, csrc, ccoef, off, dinv, b1, h1);

    // GCN layer 2
    sgemm_kernel<false, false, false><<<dim3(HID / 64, N_NODES / 128), 256>>>(
        h1, W2, nullptr, t, N_NODES, HID, HID, nullptr);
    k_gather<<<N_NODES / 2, 256>>>(t, csrc, ccoef, off, dinv, b2, h2);

    // GRU input gates for all timesteps: gi = h2 @ Wih^T + bih (read directly)
    sgemm_kernel<true, true, false><<<dim3(GI3 / 64, N_NODES / 128), 256>>>(
        h2, Wih, bih, gi, N_NODES, GI3, HID, nullptr);

    // persistent GRU (nothing runs concurrently with it)
    k_gru_all<<<128, 256, GRU_SMEM>>>(gi, Whh, bhh, hsum, hbuf, hbuf + NB * HID, bar);

    // head
    k_head<<<NB, 512>>>(hsum, focal, fc1w, fc1b, fc2w, fc2b, (float*)d_out);
}